// round 4
// baseline (speedup 1.0000x reference)
#include <cuda_runtime.h>
#include <cstdint>

// MyConvNet fused kernel, one CTA per image, 576 threads (18 warps).
//  conv1 1->64 3x3 -> 26x26 ; maxpool 3/2 -> 12x12 ; relu
//  conv2 64->64 3x3 -> 10x10 ; maxpool 3/2 -> 4x4  ; relu
//  conv3 64->10 4x4 -> 1x1   ; out [B,10]
// Key trick this round: h1 stored as duplicated (v,v) f32 pairs so the
// packed-f32x2 conv2 reads activations with one broadcast LDS.64 (no MOVs).

typedef unsigned long long ull;

__device__ __forceinline__ ull pack2(float lo, float hi) {
    ull v;
    asm("mov.b64 %0, {%1, %2};" : "=l"(v) : "f"(lo), "f"(hi));
    return v;
}
__device__ __forceinline__ void unpack2(ull v, float& lo, float& hi) {
    asm("mov.b64 {%0, %1}, %2;" : "=f"(lo), "=f"(hi) : "l"(v));
}
__device__ __forceinline__ void fma2(ull& d, ull a, ull b) {
    asm("fma.rn.f32x2 %0, %1, %2, %0;" : "+l"(d) : "l"(a), "l"(b));
}
__device__ __forceinline__ void add2(ull& d, ull a) {
    asm("add.rn.f32x2 %0, %0, %1;" : "+l"(d) : "l"(a));
}

// ---- shared memory layout (float offsets) ----
// x_s   :     0 ..   784
// w1_s  :   784 ..  1360   (64*9)
// b1_s  :  1360 ..  1424
// b2_s  :  1424 ..  1488
// h1d   :  1488 .. 18384   (64 ch * 132 pos, DUPLICATED pairs -> 8448 ull)
//                           pos = row*12+col, rows 0..10 (row 11 never read)
// w2t   : 18384 .. 57552   (576 * 68; w2 transposed [k][oc], row pad 68)
//   aliases inside w2t region (weights dead after phase-2 main loop):
//     scratch : w2t + 0      (phase-2 partials, <= 20796 floats)
//     c2_s    : w2t + 24000  (5184 floats)
//     h2_s    : w2t + 30000  (1024 floats)
#define SMEM_FLOATS 57552
#define SMEM_BYTES  (SMEM_FLOATS * 4)
#define NT 576

__global__ void __launch_bounds__(NT, 1)
convnet_kernel(const float* __restrict__ x,
               const float* __restrict__ w1, const float* __restrict__ b1,
               const float* __restrict__ w2, const float* __restrict__ b2,
               const float* __restrict__ w3, const float* __restrict__ b3,
               float* __restrict__ out)
{
    extern __shared__ float sm[];
    float* x_s  = sm;
    float* w1_s = sm + 784;
    float* b1_s = sm + 1360;
    float* b2_s = sm + 1424;
    ull*   h1d  = reinterpret_cast<ull*>(sm + 1488);   // 16B-aligned base
    float* w2t  = sm + 18384;
    float* c2_s = w2t + 24000;
    float* h2_s = w2t + 30000;

    const int tid  = threadIdx.x;
    const int img  = blockIdx.x;
    const int wid  = tid >> 5;
    const int lane = tid & 31;

    // ---------------- Phase 0: loads ----------------
    {
        const float* xg = x + img * 784;
        for (int i = tid; i < 784; i += NT) x_s[i] = xg[i];
        if (tid < 576) w1_s[tid] = w1[tid];
        if (tid < 64) { b1_s[tid] = b1[tid]; b2_s[tid] = b2[tid]; }

        // w2 transpose: w2t[k*68 + oc] = w2[oc*576 + k], vectorized LDG.128
        if (wid < 16) {
            const int ol = lane >> 3;   // 0..3
            const int kl = lane & 7;    // 0..7
            const int oc = wid * 4 + ol;
            const float4* src = reinterpret_cast<const float4*>(w2 + oc * 576);
            #pragma unroll 3
            for (int j = 0; j < 18; j++) {
                const float4 v = __ldg(src + kl + 8 * j);
                const int k = 4 * (kl + 8 * j);
                w2t[(k + 0) * 68 + oc] = v.x;
                w2t[(k + 1) * 68 + oc] = v.y;
                w2t[(k + 2) * 68 + oc] = v.z;
                w2t[(k + 3) * 68 + oc] = v.w;
            }
        }
    }
    __syncthreads();

    // ------- Phase 1: conv1 + maxpool(3,2) + relu -> h1d (duplicated) -------
    // Each task: a PAIR of adjacent pool outputs via packed f32x2.
    // Only pool rows 0..10 are needed downstream: 64 ch * 66 pairs.
    {
        const int ch = tid & 63;
        const int g0 = tid >> 6;   // 0..8
        const float bc = b1_s[ch];
        ull wp[9];
        #pragma unroll
        for (int j = 0; j < 9; j++) {
            const float w = w1_s[ch * 9 + j];
            wp[j] = pack2(w, w);
        }

        #pragma unroll 1
        for (int it = 0; it < 8; it++) {
            const int pr = g0 + 9 * it;        // 0..71
            if (pr < 66) {
                const int py  = pr / 6;            // 0..10
                const int px0 = (pr - py * 6) * 2; // 0,2,4,6,8,10

                const float* xp = x_s + (2 * py) * 28 + 2 * px0;
                // packed activation pairs: pa[r][c] = (in[r][c], in[r][c+2])
                ull pa[5][5];
                #pragma unroll
                for (int r = 0; r < 5; r++) {
                    float row[7];
                    #pragma unroll
                    for (int c = 0; c < 7; c++) row[c] = xp[r * 28 + c];
                    #pragma unroll
                    for (int c = 0; c < 5; c++) pa[r][c] = pack2(row[c], row[c + 2]);
                }

                float m0 = -3.0e38f, m1 = -3.0e38f;
                #pragma unroll
                for (int dy = 0; dy < 3; dy++)
                    #pragma unroll
                    for (int dx = 0; dx < 3; dx++) {
                        ull s2 = 0ull;
                        #pragma unroll
                        for (int r = 0; r < 3; r++)
                            #pragma unroll
                            for (int cc = 0; cc < 3; cc++)
                                fma2(s2, wp[r * 3 + cc], pa[dy + r][dx + cc]);
                        float s0, s1;
                        unpack2(s2, s0, s1);
                        m0 = fmaxf(m0, s0);
                        m1 = fmaxf(m1, s1);
                    }
                const float v0 = fmaxf(m0 + bc, 0.f);
                const float v1 = fmaxf(m1 + bc, 0.f);
                // duplicated pair store: two ulls = one STS.128 (16B aligned)
                *reinterpret_cast<float4*>(h1d + ch * 132 + py * 12 + px0) =
                    make_float4(v0, v0, v1, v1);
            }
        }
    }
    __syncthreads();

    // ------- Phase 2: conv2 at 9x9 positions, 4-way ic split -------
    // thread tile: 4 output channels x 9 positions (one output row),
    // 16 ic per group. 4 groups * 144 threads = 576.
    const int group = tid / 144;          // 0..3
    const int wi    = tid - group * 144;  // 0..143
    const int ocb   = wi & 15;            // 0..15 -> oc0 = 4*ocb
    const int yy    = wi >> 4;            // 0..8  output row
    const int oc0   = ocb * 4;

    ull acc[9][2];
    #pragma unroll
    for (int j = 0; j < 9; j++) { acc[j][0] = 0ull; acc[j][1] = 0ull; }

    {
        const int ic0 = group * 16;
        #pragma unroll 1
        for (int ic = ic0; ic < ic0 + 16; ic++) {
            const ull*  hrow = h1d + ic * 132 + yy * 12;
            const float* wk  = w2t + (ic * 9) * 68 + oc0;
            #pragma unroll
            for (int r = 0; r < 3; r++) {
                ull ap[11];
                #pragma unroll
                for (int c = 0; c < 11; c++) ap[c] = hrow[r * 12 + c]; // LDS.64
                #pragma unroll
                for (int cn = 0; cn < 3; cn++) {
                    const ulonglong2 wv = *reinterpret_cast<const ulonglong2*>(
                        wk + (r * 3 + cn) * 68);
                    #pragma unroll
                    for (int j = 0; j < 9; j++) {
                        fma2(acc[j][0], wv.x, ap[cn + j]);
                        fma2(acc[j][1], wv.y, ap[cn + j]);
                    }
                }
            }
        }
    }
    __syncthreads();  // all groups done reading w2t -> safe to reuse region

    // partials -> scratch (aliases w2t region), then packed reduction
    {
        ull* scratch = reinterpret_cast<ull*>(w2t);
        #pragma unroll
        for (int j = 0; j < 9; j++) {
            const int pos = yy * 9 + j;
            #pragma unroll
            for (int q = 0; q < 2; q++) {
                const int p = ocb * 2 + q;  // oc pair index 0..31
                scratch[(p * 81 + pos) * 4 + group + p] = acc[j][q];
            }
        }
        __syncthreads();
        for (int u = tid; u < 2592; u += NT) {
            const int p   = u / 81;
            const int pos = u - p * 81;
            const ull* s  = scratch + u * 4 + p;
            ull v = s[0];
            add2(v, s[1]);
            add2(v, s[2]);
            add2(v, s[3]);
            float lo, hi;
            unpack2(v, lo, hi);
            const int oc = 2 * p;
            c2_s[oc * 81 + pos]      = lo + b2_s[oc];
            c2_s[oc * 81 + 81 + pos] = hi + b2_s[oc + 1];
        }
    }
    __syncthreads();

    // ------- Phase 3: maxpool2(3,2) + relu -> h2 [64][16] -------
    for (int i = tid; i < 1024; i += NT) {
        const int oc = i >> 4;
        const int p  = i & 15;
        const int j  = p >> 2, ii = p & 3;
        const float* base = c2_s + oc * 81 + (2 * j) * 9 + 2 * ii;
        float m = base[0];
        #pragma unroll
        for (int dy = 0; dy < 3; dy++)
            #pragma unroll
            for (int dx = 0; dx < 3; dx++) m = fmaxf(m, base[dy * 9 + dx]);
        h2_s[oc * 16 + p] = fmaxf(m, 0.f);
    }
    __syncthreads();

    // ------- Phase 4: conv3 (10 dots over 1024), float4 both sides -------
    if (wid < 10) {
        const float4* wp = reinterpret_cast<const float4*>(w3 + (wid << 10));
        const float4* hp = reinterpret_cast<const float4*>(h2_s);
        float sres = 0.f;
        #pragma unroll
        for (int m = 0; m < 8; m++) {
            const float4 wv = __ldg(wp + lane + 32 * m);
            const float4 hv = hp[lane + 32 * m];
            sres = fmaf(wv.x, hv.x, sres);
            sres = fmaf(wv.y, hv.y, sres);
            sres = fmaf(wv.z, hv.z, sres);
            sres = fmaf(wv.w, hv.w, sres);
        }
        #pragma unroll
        for (int off = 16; off > 0; off >>= 1)
            sres += __shfl_down_sync(0xffffffffu, sres, off);
        if (lane == 0) out[img * 10 + wid] = sres + b3[wid];
    }
}

extern "C" void kernel_launch(void* const* d_in, const int* in_sizes, int n_in,
                              void* d_out, int out_size)
{
    const float* x  = (const float*)d_in[0];
    const float* w1 = (const float*)d_in[1];
    const float* b1 = (const float*)d_in[2];
    const float* w2 = (const float*)d_in[3];
    const float* b2 = (const float*)d_in[4];
    const float* w3 = (const float*)d_in[5];
    const float* b3 = (const float*)d_in[6];
    float* out = (float*)d_out;

    const int B = in_sizes[0] / 784;

    cudaFuncSetAttribute(convnet_kernel,
                         cudaFuncAttributeMaxDynamicSharedMemorySize, SMEM_BYTES);

    convnet_kernel<<<B, NT, SMEM_BYTES>>>(x, w1, b1, w2, b2, w3, b3, out);
}

// round 5
// speedup vs baseline: 1.0528x; 1.0528x over previous
#include <cuda_runtime.h>
#include <cstdint>

// MyConvNet fused kernel, one CTA per image, 576 threads (18 warps).
//  conv1 1->64 3x3 -> 26x26 ; maxpool 3/2 -> 12x12 ; relu
//  conv2 64->64 3x3 -> 10x10 ; maxpool 3/2 -> 4x4  ; relu
//  conv3 64->10 4x4 -> 1x1   ; out [B,10]
// h1 stored as duplicated (v,v) f32 pairs so packed-f32x2 conv2 reads
// activations with one broadcast LDS.64 (no pack MOVs). ch-stride 134 ull
// makes the phase-1 STS.128 stores bank-conflict-free (268 words % 32 = 12).

typedef unsigned long long ull;

__device__ __forceinline__ ull pack2(float lo, float hi) {
    ull v;
    asm("mov.b64 %0, {%1, %2};" : "=l"(v) : "f"(lo), "f"(hi));
    return v;
}
__device__ __forceinline__ void unpack2(ull v, float& lo, float& hi) {
    asm("mov.b64 {%0, %1}, %2;" : "=f"(lo), "=f"(hi) : "l"(v));
}
__device__ __forceinline__ void fma2(ull& d, ull a, ull b) {
    asm("fma.rn.f32x2 %0, %1, %2, %0;" : "+l"(d) : "l"(a), "l"(b));
}
__device__ __forceinline__ void add2(ull& d, ull a) {
    asm("add.rn.f32x2 %0, %0, %1;" : "+l"(d) : "l"(a));
}

// ---- shared memory layout (float offsets) ----
// x_s   :     0 ..   784
// w1_s  :   784 ..  1360   (64*9)
// b1_s  :  1360 ..  1424
// b2_s  :  1424 ..  1488
// h1d   :  1488 .. 18640   (64 ch * 134-ull stride, duplicated pairs;
//                           pos = row*12+col, rows 0..10; row 11 never read)
// w2t   : 18640 .. 57808   (576 * 68; w2 transposed [k][oc], row pad 68)
//   aliases inside w2t region (weights dead after phase-2 main loop):
//     scratch : w2t + 0      (phase-2 partials, <= 20796 floats)
//     c2_s    : w2t + 24000  (5184 floats)
//     h2_s    : w2t + 30000  (1024 floats)
#define SMEM_FLOATS 57808
#define SMEM_BYTES  (SMEM_FLOATS * 4)
#define NT 576
#define H1_STRIDE 134

__global__ void __launch_bounds__(NT, 1)
convnet_kernel(const float* __restrict__ x,
               const float* __restrict__ w1, const float* __restrict__ b1,
               const float* __restrict__ w2, const float* __restrict__ b2,
               const float* __restrict__ w3, const float* __restrict__ b3,
               float* __restrict__ out)
{
    extern __shared__ float sm[];
    float* x_s  = sm;
    float* w1_s = sm + 784;
    float* b1_s = sm + 1360;
    float* b2_s = sm + 1424;
    ull*   h1d  = reinterpret_cast<ull*>(sm + 1488);   // 16B-aligned base
    float* w2t  = sm + 18640;
    float* c2_s = w2t + 24000;
    float* h2_s = w2t + 30000;

    const int tid  = threadIdx.x;
    const int img  = blockIdx.x;
    const int wid  = tid >> 5;
    const int lane = tid & 31;

    // ---------------- Phase 0: loads ----------------
    {
        const float* xg = x + img * 784;
        for (int i = tid; i < 784; i += NT) x_s[i] = xg[i];
        if (tid < 576) w1_s[tid] = w1[tid];
        if (tid < 64) { b1_s[tid] = b1[tid]; b2_s[tid] = b2[tid]; }

        // w2 transpose: w2t[k*68 + oc] = w2[oc*576 + k], vectorized LDG.128
        if (wid < 16) {
            const int ol = lane >> 3;   // 0..3
            const int kl = lane & 7;    // 0..7
            const int oc = wid * 4 + ol;
            const float4* src = reinterpret_cast<const float4*>(w2 + oc * 576);
            #pragma unroll 3
            for (int j = 0; j < 18; j++) {
                const float4 v = __ldg(src + kl + 8 * j);
                const int k = 4 * (kl + 8 * j);
                w2t[(k + 0) * 68 + oc] = v.x;
                w2t[(k + 1) * 68 + oc] = v.y;
                w2t[(k + 2) * 68 + oc] = v.z;
                w2t[(k + 3) * 68 + oc] = v.w;
            }
        }
    }
    __syncthreads();

    // ------- Phase 1: conv1 + maxpool(3,2) + relu -> h1d (duplicated) -------
    // Each task: a PAIR of adjacent pool outputs via packed f32x2.
    // Only pool rows 0..10 are needed downstream: 64 ch * 66 pairs.
    {
        const int ch = tid & 63;
        const int g0 = tid >> 6;   // 0..8
        const float bc = b1_s[ch];
        ull wp[9];
        #pragma unroll
        for (int j = 0; j < 9; j++) {
            const float w = w1_s[ch * 9 + j];
            wp[j] = pack2(w, w);
        }

        #pragma unroll 1
        for (int it = 0; it < 8; it++) {
            const int pr = g0 + 9 * it;        // 0..71
            if (pr < 66) {
                const int py  = pr / 6;            // 0..10
                const int px0 = (pr - py * 6) * 2; // 0,2,4,6,8,10

                const float* xp = x_s + (2 * py) * 28 + 2 * px0;
                // packed activation pairs: pa[r][c] = (in[r][c], in[r][c+2])
                ull pa[5][5];
                #pragma unroll
                for (int r = 0; r < 5; r++) {
                    float row[7];
                    #pragma unroll
                    for (int c = 0; c < 7; c++) row[c] = xp[r * 28 + c];
                    #pragma unroll
                    for (int c = 0; c < 5; c++) pa[r][c] = pack2(row[c], row[c + 2]);
                }

                float m0 = -3.0e38f, m1 = -3.0e38f;
                #pragma unroll
                for (int dy = 0; dy < 3; dy++)
                    #pragma unroll
                    for (int dx = 0; dx < 3; dx++) {
                        ull s2 = 0ull;
                        #pragma unroll
                        for (int r = 0; r < 3; r++)
                            #pragma unroll
                            for (int cc = 0; cc < 3; cc++)
                                fma2(s2, wp[r * 3 + cc], pa[dy + r][dx + cc]);
                        float s0, s1;
                        unpack2(s2, s0, s1);
                        m0 = fmaxf(m0, s0);
                        m1 = fmaxf(m1, s1);
                    }
                const float v0 = fmaxf(m0 + bc, 0.f);
                const float v1 = fmaxf(m1 + bc, 0.f);
                // duplicated pair store: one STS.128, conflict-free banks
                *reinterpret_cast<float4*>(h1d + ch * H1_STRIDE + py * 12 + px0) =
                    make_float4(v0, v0, v1, v1);
            }
        }
    }
    __syncthreads();

    // ------- Phase 2: conv2 at 9x9 positions, 4-way ic split -------
    // thread tile: 4 output channels x 9 positions (one output row),
    // 16 ic per group. 4 groups * 144 threads = 576.
    const int group = tid / 144;          // 0..3
    const int wi    = tid - group * 144;  // 0..143
    const int ocb   = wi & 15;            // 0..15 -> oc0 = 4*ocb
    const int yy    = wi >> 4;            // 0..8  output row
    const int oc0   = ocb * 4;

    ull acc[9][2];
    #pragma unroll
    for (int j = 0; j < 9; j++) { acc[j][0] = 0ull; acc[j][1] = 0ull; }

    {
        const int ic0 = group * 16;
        #pragma unroll 1
        for (int ic = ic0; ic < ic0 + 16; ic++) {
            const ull*  hrow = h1d + ic * H1_STRIDE + yy * 12;
            const float* wk  = w2t + (ic * 9) * 68 + oc0;
            #pragma unroll
            for (int r = 0; r < 3; r++) {
                ull ap[11];
                #pragma unroll
                for (int c = 0; c < 11; c++) ap[c] = hrow[r * 12 + c]; // LDS.64
                #pragma unroll
                for (int cn = 0; cn < 3; cn++) {
                    const ulonglong2 wv = *reinterpret_cast<const ulonglong2*>(
                        wk + (r * 3 + cn) * 68);
                    #pragma unroll
                    for (int j = 0; j < 9; j++) {
                        fma2(acc[j][0], wv.x, ap[cn + j]);
                        fma2(acc[j][1], wv.y, ap[cn + j]);
                    }
                }
            }
        }
    }
    __syncthreads();  // all groups done reading w2t -> safe to reuse region

    // partials -> scratch (aliases w2t region), then packed reduction
    {
        ull* scratch = reinterpret_cast<ull*>(w2t);
        #pragma unroll
        for (int j = 0; j < 9; j++) {
            const int pos = yy * 9 + j;
            #pragma unroll
            for (int q = 0; q < 2; q++) {
                const int p = ocb * 2 + q;  // oc pair index 0..31
                scratch[(p * 81 + pos) * 4 + group + p] = acc[j][q];
            }
        }
        __syncthreads();
        for (int u = tid; u < 2592; u += NT) {
            const int p   = u / 81;
            const int pos = u - p * 81;
            const ull* s  = scratch + u * 4 + p;
            ull v = s[0];
            add2(v, s[1]);
            add2(v, s[2]);
            add2(v, s[3]);
            float lo, hi;
            unpack2(v, lo, hi);
            const int oc = 2 * p;
            c2_s[oc * 81 + pos]      = lo + b2_s[oc];
            c2_s[oc * 81 + 81 + pos] = hi + b2_s[oc + 1];
        }
    }
    __syncthreads();

    // ------- Phase 3: maxpool2(3,2) + relu -> h2 [64][16] -------
    for (int i = tid; i < 1024; i += NT) {
        const int oc = i >> 4;
        const int p  = i & 15;
        const int j  = p >> 2, ii = p & 3;
        const float* base = c2_s + oc * 81 + (2 * j) * 9 + 2 * ii;
        float m = base[0];
        #pragma unroll
        for (int dy = 0; dy < 3; dy++)
            #pragma unroll
            for (int dx = 0; dx < 3; dx++) m = fmaxf(m, base[dy * 9 + dx]);
        h2_s[oc * 16 + p] = fmaxf(m, 0.f);
    }
    __syncthreads();

    // ------- Phase 4: conv3 (10 dots over 1024), float4 both sides -------
    if (wid < 10) {
        const float4* wp = reinterpret_cast<const float4*>(w3 + (wid << 10));
        const float4* hp = reinterpret_cast<const float4*>(h2_s);
        float sres = 0.f;
        #pragma unroll
        for (int m = 0; m < 8; m++) {
            const float4 wv = __ldg(wp + lane + 32 * m);
            const float4 hv = hp[lane + 32 * m];
            sres = fmaf(wv.x, hv.x, sres);
            sres = fmaf(wv.y, hv.y, sres);
            sres = fmaf(wv.z, hv.z, sres);
            sres = fmaf(wv.w, hv.w, sres);
        }
        #pragma unroll
        for (int off = 16; off > 0; off >>= 1)
            sres += __shfl_down_sync(0xffffffffu, sres, off);
        if (lane == 0) out[img * 10 + wid] = sres + b3[wid];
    }
}

extern "C" void kernel_launch(void* const* d_in, const int* in_sizes, int n_in,
                              void* d_out, int out_size)
{
    const float* x  = (const float*)d_in[0];
    const float* w1 = (const float*)d_in[1];
    const float* b1 = (const float*)d_in[2];
    const float* w2 = (const float*)d_in[3];
    const float* b2 = (const float*)d_in[4];
    const float* w3 = (const float*)d_in[5];
    const float* b3 = (const float*)d_in[6];
    float* out = (float*)d_out;

    const int B = in_sizes[0] / 784;

    cudaFuncSetAttribute(convnet_kernel,
                         cudaFuncAttributeMaxDynamicSharedMemorySize, SMEM_BYTES);

    convnet_kernel<<<B, NT, SMEM_BYTES>>>(x, w1, b1, w2, b2, w3, b3, out);
}